// round 2
// baseline (speedup 1.0000x reference)
#include <cuda_runtime.h>
#include <math.h>

#define NB 8
#define NJ 17
#define NV 64
#define NPAIR (NB * NJ)             // 136
#define VOX (NV * NV * NV)          // 262144
#define SPLIT 32
#define NBLOCKS (NPAIR * SPLIT)     // 4352
#define THREADS 256
#define CHUNK (VOX / SPLIT)         // 8192 elements per block
#define ITERS (CHUNK / 4 / THREADS) // 8 float4 per thread

__device__ float g_partials[NBLOCKS];
__device__ unsigned int g_done = 0;   // zero-initialized; last block resets it each launch

__device__ __forceinline__ int grid_idx(float l, float c) {
    float norm = (l - c) * (1.0f / 1000.0f);        // box_range = 1000
    int idx = (int)floorf((norm + 1.0f) * 0.5f * (float)(NV - 1));
    idx = idx < 0 ? 0 : (idx > NV - 1 ? NV - 1 : idx);
    return idx;
}

__global__ __launch_bounds__(THREADS)
void vol_ce_loss_kernel(const float* __restrict__ vol,
                        const float* __restrict__ label,
                        const float* __restrict__ center,
                        float* __restrict__ out) {
    const int blk  = blockIdx.x;            // 0 .. NBLOCKS-1
    const int pair = blk / SPLIT;
    const int part = blk % SPLIT;
    const int t    = threadIdx.x;

    // ---- phase 1: streaming sum-of-exp over this block's contiguous chunk ----
    const float4* base = reinterpret_cast<const float4*>(
        vol + (size_t)pair * VOX + (size_t)part * CHUNK);

    float s0 = 0.0f, s1 = 0.0f;
#pragma unroll
    for (int i = 0; i < ITERS; ++i) {
        float4 v = __ldg(base + i * THREADS + t);
        s0 += __expf(v.x) + __expf(v.y);
        s1 += __expf(v.z) + __expf(v.w);
    }
    float s = s0 + s1;

#pragma unroll
    for (int off = 16; off > 0; off >>= 1)
        s += __shfl_down_sync(0xFFFFFFFFu, s, off);

    __shared__ float sh[THREADS / 32];
    const int lane = t & 31;
    const int wid  = t >> 5;
    if (lane == 0) sh[wid] = s;
    __syncthreads();

    __shared__ bool amLast;
    if (t == 0) {
        float v = 0.0f;
#pragma unroll
        for (int k = 0; k < THREADS / 32; ++k) v += sh[k];
        g_partials[blk] = v;
        __threadfence();
        unsigned int prev = atomicAdd(&g_done, 1u);
        amLast = (prev == NBLOCKS - 1);
    }
    __syncthreads();

    // ---- phase 2: only the last-arriving block computes the loss ----
    if (!amLast) return;

    __shared__ float shr[256];
    float term = 0.0f;
    if (t < NPAIR) {
        const int b = t / NJ;

        float S = 0.0f;
#pragma unroll
        for (int k = 0; k < SPLIT; ++k)
            S += g_partials[t * SPLIT + k];

        const float cx = center[b * 3 + 0];
        const float cy = center[b * 3 + 1];
        const float cz = center[b * 3 + 2];
        const float lx = label[t * 3 + 0];
        const float ly = label[t * 3 + 1];
        const float lz = label[t * 3 + 2];

        const int ix = grid_idx(lx, cx);
        const int iy = grid_idx(ly, cy);
        const int iz = grid_idx(lz, cz);
        const int flat = (ix * NV + iy) * NV + iz;

        const float x = vol[(size_t)t * VOX + flat];
        const float p = __expf(x) / S;
        term = -logf(p + 1e-6f) * 0.01f;   // beta = 0.01
    }
    shr[t] = term;
    __syncthreads();
#pragma unroll
    for (int sdist = 128; sdist > 0; sdist >>= 1) {
        if (t < sdist) shr[t] += shr[t + sdist];
        __syncthreads();
    }
    if (t == 0) {
        out[0] = shr[0] * (1.0f / (float)NPAIR);
        g_done = 0;   // reset for the next graph replay (deterministic)
    }
}

extern "C" void kernel_launch(void* const* d_in, const int* in_sizes, int n_in,
                              void* d_out, int out_size) {
    const float* vol    = (const float*)d_in[0];
    const float* label  = (const float*)d_in[1];
    const float* center = (const float*)d_in[2];
    float* out = (float*)d_out;

    vol_ce_loss_kernel<<<NBLOCKS, THREADS>>>(vol, label, center, out);
}

// round 3
// speedup vs baseline: 1.0685x; 1.0685x over previous
#include <cuda_runtime.h>
#include <math.h>

#define NB 8
#define NJ 17
#define NV 64
#define NPAIR (NB * NJ)             // 136
#define VOX (NV * NV * NV)          // 262144
#define SPLIT 16
#define NBLOCKS (NPAIR * SPLIT)     // 2176
#define THREADS 256
#define CHUNK (VOX / SPLIT)         // 16384 elements per block
#define ITERS (CHUNK / 4 / THREADS) // 16 float4 per thread
#define GROUP 4                     // pipelined prefetch depth (float4s)

__device__ float g_pairsum[NPAIR];    // zero-init at load; reset by last block each launch
__device__ unsigned int g_done = 0;

__device__ __forceinline__ int grid_idx(float l, float c) {
    float norm = (l - c) * (1.0f / 1000.0f);        // box_range = 1000
    int idx = (int)floorf((norm + 1.0f) * 0.5f * (float)(NV - 1));
    idx = idx < 0 ? 0 : (idx > NV - 1 ? NV - 1 : idx);
    return idx;
}

__device__ __forceinline__ float exp4sum(float4 v) {
    return (__expf(v.x) + __expf(v.y)) + (__expf(v.z) + __expf(v.w));
}

__global__ __launch_bounds__(THREADS, 4)
void vol_ce_loss_kernel(const float* __restrict__ vol,
                        const float* __restrict__ label,
                        const float* __restrict__ center,
                        float* __restrict__ out) {
    const int blk  = blockIdx.x;            // 0 .. NBLOCKS-1
    const int pair = blk / SPLIT;
    const int part = blk % SPLIT;
    const int t    = threadIdx.x;

    // ---- phase 1: streaming sum-of-exp, software-pipelined float4 loads ----
    const float4* p = reinterpret_cast<const float4*>(
        vol + (size_t)pair * VOX + (size_t)part * CHUNK) + t;

    float4 a0 = __ldg(p + 0 * THREADS);
    float4 a1 = __ldg(p + 1 * THREADS);
    float4 a2 = __ldg(p + 2 * THREADS);
    float4 a3 = __ldg(p + 3 * THREADS);

    float s0 = 0.0f, s1 = 0.0f;
#pragma unroll
    for (int g = 0; g < ITERS / GROUP; ++g) {
        float4 b0, b1, b2, b3;
        if (g < ITERS / GROUP - 1) {
            const float4* q = p + (g + 1) * GROUP * THREADS;
            b0 = __ldg(q + 0 * THREADS);
            b1 = __ldg(q + 1 * THREADS);
            b2 = __ldg(q + 2 * THREADS);
            b3 = __ldg(q + 3 * THREADS);
        }
        s0 += exp4sum(a0);
        s1 += exp4sum(a1);
        s0 += exp4sum(a2);
        s1 += exp4sum(a3);
        a0 = b0; a1 = b1; a2 = b2; a3 = b3;
    }
    float s = s0 + s1;

#pragma unroll
    for (int off = 16; off > 0; off >>= 1)
        s += __shfl_down_sync(0xFFFFFFFFu, s, off);

    __shared__ float sh[THREADS / 32];
    const int lane = t & 31;
    const int wid  = t >> 5;
    if (lane == 0) sh[wid] = s;
    __syncthreads();

    __shared__ bool amLast;
    if (t == 0) {
        float v = 0.0f;
#pragma unroll
        for (int k = 0; k < THREADS / 32; ++k) v += sh[k];
        atomicAdd(&g_pairsum[pair], v);
        __threadfence();
        unsigned int prev = atomicAdd(&g_done, 1u);
        amLast = (prev == NBLOCKS - 1);
    }
    __syncthreads();

    // ---- phase 2: only the last-arriving block computes the loss ----
    if (!amLast) return;

    __shared__ float shr[256];
    float term = 0.0f;
    float S = 0.0f;
    if (t < NPAIR) {
        const int b = t / NJ;
        S = g_pairsum[t];

        const float cx = center[b * 3 + 0];
        const float cy = center[b * 3 + 1];
        const float cz = center[b * 3 + 2];
        const float lx = label[t * 3 + 0];
        const float ly = label[t * 3 + 1];
        const float lz = label[t * 3 + 2];

        const int ix = grid_idx(lx, cx);
        const int iy = grid_idx(ly, cy);
        const int iz = grid_idx(lz, cz);
        const int flat = (ix * NV + iy) * NV + iz;

        const float x = vol[(size_t)t * VOX + flat];
        const float pprob = __expf(x) / S;
        term = -logf(pprob + 1e-6f) * 0.01f;   // beta = 0.01
    }
    shr[t] = term;
    __syncthreads();
#pragma unroll
    for (int sdist = 128; sdist > 0; sdist >>= 1) {
        if (t < sdist) shr[t] += shr[t + sdist];
        __syncthreads();
    }
    if (t == 0) {
        out[0] = shr[0] * (1.0f / (float)NPAIR);
        g_done = 0;
    }
    // reset pair accumulators for the next graph replay
    if (t < NPAIR) g_pairsum[t] = 0.0f;
}

extern "C" void kernel_launch(void* const* d_in, const int* in_sizes, int n_in,
                              void* d_out, int out_size) {
    const float* vol    = (const float*)d_in[0];
    const float* label  = (const float*)d_in[1];
    const float* center = (const float*)d_in[2];
    float* out = (float*)d_out;

    vol_ce_loss_kernel<<<NBLOCKS, THREADS>>>(vol, label, center, out);
}